// round 12
// baseline (speedup 1.0000x reference)
#include <cuda_runtime.h>
#include <cuda_fp16.h>
#include <cstdint>

#define N_FRAMES 65536
#define H_DIM    512
#define GVDIM    640
#define VNUM     320
#define DDIM     128

// --------------------------- device scratch --------------------------------
__device__ float g_logits[(size_t)N_FRAMES * GVDIM];   // 160 MiB
__device__ float g_marginal[GVDIM];
__device__ __half g_A0[(size_t)N_FRAMES * H_DIM];      // 64 MiB
__device__ __half g_A1[(size_t)N_FRAMES * H_DIM];      // 64 MiB
__device__ __half g_B0[GVDIM * H_DIM];                 // W^T split hi [640][512]
__device__ __half g_B1[GVDIM * H_DIM];                 // W^T split lo

// --------------------------- helpers ---------------------------------------
__device__ __forceinline__ uint32_t smem_u32(const void* p) {
    uint32_t a;
    asm("{ .reg .u64 t; cvta.to.shared.u64 t, %1; cvt.u32.u64 %0, t; }"
        : "=r"(a) : "l"(p));
    return a;
}

__device__ __forceinline__ void cp_async16(uint32_t saddr, const void* gaddr) {
    asm volatile("cp.async.cg.shared.global [%0], [%1], 16;"
                 :: "r"(saddr), "l"(gaddr) : "memory");
}

__device__ __forceinline__ void ldsm4(uint32_t r[4], uint32_t addr) {
    asm volatile("ldmatrix.sync.aligned.m8n8.x4.shared.b16 {%0,%1,%2,%3}, [%4];"
                 : "=r"(r[0]), "=r"(r[1]), "=r"(r[2]), "=r"(r[3]) : "r"(addr));
}

// fp32-accumulate HMMA
__device__ __forceinline__ void mma16816(float c[4], const uint32_t a[4],
                                         const uint32_t b[2]) {
    asm volatile(
        "mma.sync.aligned.m16n8k16.row.col.f32.f16.f16.f32 "
        "{%0,%1,%2,%3}, {%4,%5,%6,%7}, {%8,%9}, {%0,%1,%2,%3};"
        : "+f"(c[0]), "+f"(c[1]), "+f"(c[2]), "+f"(c[3])
        : "r"(a[0]), "r"(a[1]), "r"(a[2]), "r"(a[3]), "r"(b[0]), "r"(b[1]));
}

// fp16-accumulate HMMA (D/C are 2 x f16x2 regs)
__device__ __forceinline__ void mma16816_h(uint32_t d[2], const uint32_t a[4],
                                           const uint32_t b[2]) {
    asm volatile(
        "mma.sync.aligned.m16n8k16.row.col.f16.f16.f16.f16 "
        "{%0,%1}, {%2,%3,%4,%5}, {%6,%7}, {%0,%1};"
        : "+r"(d[0]), "+r"(d[1])
        : "r"(a[0]), "r"(a[1]), "r"(a[2]), "r"(a[3]), "r"(b[0]), "r"(b[1]));
}

// ---------------------------------------------------------------------------
// ~1-ulp log (fast-math proof)
// ---------------------------------------------------------------------------
__device__ __forceinline__ float acc_logf(float x) {
    int   ix = __float_as_int(x);
    int   e  = ((ix >> 23) & 0xff) - 126;
    float m  = __int_as_float((ix & 0x007fffff) | 0x3f000000);
    if (m < 0.70710678118654752f) { m += m; e -= 1; }
    float f = m - 1.0f;
    float z = f * f;
    float p = 7.0376836292e-2f;
    p = fmaf(p, f, -1.1514610310e-1f);
    p = fmaf(p, f,  1.1676998740e-1f);
    p = fmaf(p, f, -1.2420140846e-1f);
    p = fmaf(p, f,  1.4249322787e-1f);
    p = fmaf(p, f, -1.6668057665e-1f);
    p = fmaf(p, f,  2.0000714765e-1f);
    p = fmaf(p, f, -2.4999993993e-1f);
    p = fmaf(p, f,  3.3333331174e-1f);
    p = p * f * z;
    float ef = (float)e;
    p = fmaf(-0.5f, z, p);
    float r = fmaf(ef, -2.12194440e-4f, p);
    r = r + f;
    r = fmaf(ef, 0.693359375f, r);
    return r;
}

// ---------------------------------------------------------------------------
// fp16 2-way exact-residual splits
// ---------------------------------------------------------------------------
__device__ __forceinline__ void split2(float v, __half& h0, __half& h1) {
    h0 = __float2half_rn(v);
    h1 = __float2half_rn(v - __half2float(h0));
}

__global__ __launch_bounds__(1024) void split_a_kernel(const float* __restrict__ A) {
    size_t i = (size_t)blockIdx.x * blockDim.x + threadIdx.x;  // float4 index
    float4 x = reinterpret_cast<const float4*>(A)[i];
    float v[4] = {x.x, x.y, x.z, x.w};
    __half h0[4], h1[4];
#pragma unroll
    for (int c = 0; c < 4; c++) split2(v[c], h0[c], h1[c]);
    __half2* p0 = reinterpret_cast<__half2*>(g_A0);
    __half2* p1 = reinterpret_cast<__half2*>(g_A1);
    p0[2 * i]     = __half2(h0[0], h0[1]);
    p0[2 * i + 1] = __half2(h0[2], h0[3]);
    p1[2 * i]     = __half2(h1[0], h1[1]);
    p1[2 * i + 1] = __half2(h1[2], h1[3]);
}

// W[k][n] -> B[n][k]; also zeroes g_marginal (fused init)
__global__ __launch_bounds__(512) void split_b_kernel(const float* __restrict__ W) {
    int n = blockIdx.x;       // 0..639
    int k = threadIdx.x;      // 0..511
    if (k == 0) g_marginal[n] = 0.0f;
    float v = W[(size_t)k * GVDIM + n];
    __half h0, h1;
    split2(v, h0, h1);
    g_B0[(size_t)n * H_DIM + k] = h0;
    g_B1[(size_t)n * H_DIM + k] = h1;
}

// ---------------------------------------------------------------------------
// GEMM v3: mixed-precision accumulators. a0b0 -> fp32 acc; a0b1, a1b0 -> fp16
// acc (magnitudes ~2^-12, converted to fp32 once at the end).
// BM=64, BN=128, BK=32; 256 threads; 8 warps (2m x 4n), warp tile 32x32.
// Double-buffered smem, 80B padded rows, ONE sync per stage.
// ---------------------------------------------------------------------------
#define STG_BYTES   30720          // A: 2x(64x80)=10240, B: 2x(128x80)=20480
#define SMEM_BYTES  (2 * STG_BYTES)

__global__ __launch_bounds__(256, 2) void gemm_kernel(const float* __restrict__ bias) {
    extern __shared__ char smem[];
    const uint32_t sb = smem_u32(smem);
    const int tid  = threadIdx.x;
    const int wid  = tid >> 5;
    const int lane = tid & 31;
    const int wm = wid >> 2;           // 0..1
    const int wn = wid & 3;            // 0..3
    const int m0 = blockIdx.y * 64;
    const int n0 = blockIdx.x * 128;

    float acc[2][4][4];
    uint32_t acch0[2][4][2];           // a0*b1, fp16 pairs
    uint32_t acch1[2][4][2];           // a1*b0, fp16 pairs
#pragma unroll
    for (int mf = 0; mf < 2; mf++)
#pragma unroll
        for (int nf = 0; nf < 4; nf++) {
#pragma unroll
            for (int c = 0; c < 4; c++) acc[mf][nf][c] = 0.0f;
            acch0[mf][nf][0] = 0u; acch0[mf][nf][1] = 0u;
            acch1[mf][nf][0] = 0u; acch1[mf][nf][1] = 0u;
        }

    // ---- loader: 6 x 16B per thread per stage ----
    const int r0 = tid >> 2;                 // 0..63
    const int kc = tid & 3;
    const __half* pA0 = g_A0 + (size_t)(m0 + r0) * H_DIM + kc * 8;
    const __half* pA1 = g_A1 + (size_t)(m0 + r0) * H_DIM + kc * 8;
    const __half* pB0 = g_B0 + (size_t)(n0 + r0) * H_DIM + kc * 8;
    const __half* pB1 = g_B1 + (size_t)(n0 + r0) * H_DIM + kc * 8;
    const uint32_t sA = sb + r0 * 80 + kc * 16;            // A region base
    const uint32_t sB = sb + 10240 + r0 * 80 + kc * 16;    // B region base
    const size_t ROW64 = (size_t)64 * H_DIM;

    auto issue_stage = [&](int s) {
        const int off = s * 32;
        const uint32_t buf = (uint32_t)(s & 1) * STG_BYTES;
        cp_async16(sA + buf,                 pA0 + off);
        cp_async16(sA + buf + 5120,          pA1 + off);
        cp_async16(sB + buf,                 pB0 + off);
        cp_async16(sB + buf + 5120,          pB0 + off + ROW64);
        cp_async16(sB + buf + 10240,         pB1 + off);
        cp_async16(sB + buf + 10240 + 5120,  pB1 + off + ROW64);
        asm volatile("cp.async.commit_group;" ::: "memory");
    };

    issue_stage(0);

    const int a_row = wm * 32 + (lane & 15);
    const int a_kc  = (lane >> 4) * 16;
    const int b_row = wn * 32 + ((lane >> 4) & 1) * 8 + (lane & 7);
    const int b_kc  = ((lane >> 3) & 1) * 16;

    for (int s = 0; s < 16; s++) {
        asm volatile("cp.async.wait_group 0;" ::: "memory");
        __syncthreads();
        if (s + 1 < 16) issue_stage(s + 1);

        const uint32_t abase = sb + (s & 1) * STG_BYTES;         // A0
        const uint32_t bbase = abase + 10240;                    // B0 (B1 at +10240)

#pragma unroll
        for (int ks = 0; ks < 2; ks++) {
            uint32_t Bf[2][8];
#pragma unroll
            for (int s2 = 0; s2 < 2; s2++)
#pragma unroll
                for (int p = 0; p < 2; p++)
                    ldsm4(&Bf[s2][p * 4], bbase + s2 * 10240 +
                          (b_row + p * 16) * 80 + ks * 32 + b_kc);

            uint32_t Af[2][4];
#pragma unroll
            for (int mf = 0; mf < 2; mf++)
                ldsm4(Af[mf], abase + (a_row + mf * 16) * 80 + ks * 32 + a_kc);
            // a0*b0 -> fp32 acc
#pragma unroll
            for (int mf = 0; mf < 2; mf++)
#pragma unroll
                for (int nf = 0; nf < 4; nf++)
                    mma16816(acc[mf][nf], Af[mf], &Bf[0][nf * 2]);
            // a0*b1 -> fp16 acc
#pragma unroll
            for (int mf = 0; mf < 2; mf++)
#pragma unroll
                for (int nf = 0; nf < 4; nf++)
                    mma16816_h(acch0[mf][nf], Af[mf], &Bf[1][nf * 2]);
            // a1*b0 -> fp16 acc
#pragma unroll
            for (int mf = 0; mf < 2; mf++)
                ldsm4(Af[mf], abase + 5120 + (a_row + mf * 16) * 80 + ks * 32 + a_kc);
#pragma unroll
            for (int mf = 0; mf < 2; mf++)
#pragma unroll
                for (int nf = 0; nf < 4; nf++)
                    mma16816_h(acch1[mf][nf], Af[mf], &Bf[0][nf * 2]);
        }
    }

    // ---- merge fp16 accs, add bias, store ----
    const int gID = lane >> 2;
    const int tig = lane & 3;
    float2 bv[4];
#pragma unroll
    for (int nf = 0; nf < 4; nf++)
        bv[nf] = *reinterpret_cast<const float2*>(bias + n0 + wn * 32 + nf * 8 + tig * 2);

#pragma unroll
    for (int mf = 0; mf < 2; mf++) {
        const int m = m0 + wm * 32 + mf * 16 + gID;
#pragma unroll
        for (int nf = 0; nf < 4; nf++) {
            const int n = n0 + wn * 32 + nf * 8 + tig * 2;
            float2 h00 = __half22float2(*reinterpret_cast<__half2*>(&acch0[mf][nf][0]));
            float2 h01 = __half22float2(*reinterpret_cast<__half2*>(&acch0[mf][nf][1]));
            float2 h10 = __half22float2(*reinterpret_cast<__half2*>(&acch1[mf][nf][0]));
            float2 h11 = __half22float2(*reinterpret_cast<__half2*>(&acch1[mf][nf][1]));
            float c0 = acc[mf][nf][0] + h00.x + h10.x;
            float c1 = acc[mf][nf][1] + h00.y + h10.y;
            float c2 = acc[mf][nf][2] + h01.x + h11.x;
            float c3 = acc[mf][nf][3] + h01.y + h11.y;
            float2 v0 = {c0 + bv[nf].x, c1 + bv[nf].y};
            float2 v1 = {c2 + bv[nf].x, c3 + bv[nf].y};
            *reinterpret_cast<float2*>(g_logits + (size_t)m * GVDIM + n)       = v0;
            *reinterpret_cast<float2*>(g_logits + (size_t)(m + 8) * GVDIM + n) = v1;
        }
    }
}

// ---------------------------------------------------------------------------
// Epilogue (exact R8 form): one warp per (n,g) pair; 8 pairs per warp;
// 2048 blocks x 256 threads. Approx-filter argmax, exact only for candidates.
// ---------------------------------------------------------------------------
__global__ __launch_bounds__(256) void epilogue_kernel(
    const float* __restrict__ gumbel_u,
    const float* __restrict__ codevectors,
    float* __restrict__ out)
{
    const unsigned FULL = 0xffffffffu;
    __shared__ float smar[GVDIM];
    const int tid  = threadIdx.x;
    const int warp = blockIdx.x * 8 + (tid >> 5);
    const int lane = tid & 31;

    for (int i = tid; i < GVDIM; i += 256) smar[i] = 0.0f;
    __syncthreads();

    float macc[2][10];
#pragma unroll
    for (int g = 0; g < 2; g++)
#pragma unroll
        for (int j = 0; j < 10; j++) macc[g][j] = 0.0f;

    const int p0 = warp * 8;
    for (int i = 0; i < 8; i++) {
        const int p = p0 + i;
        const int n = p >> 1;
        const int g = p & 1;
        const float* lrow = g_logits + (size_t)n * GVDIM + g * VNUM;
        const float* urow = gumbel_u + (size_t)p * VNUM;

        float l[10], u[10], za[10];
#pragma unroll
        for (int jj = 0; jj < 5; jj++) {
            const int e0 = 2 * (lane + 32 * jj);
            float2 lf = *reinterpret_cast<const float2*>(lrow + e0);
            float2 uf = *reinterpret_cast<const float2*>(urow + e0);
            l[2 * jj] = lf.x; l[2 * jj + 1] = lf.y;
            u[2 * jj] = uf.x; u[2 * jj + 1] = uf.y;
        }

        float lmax = -3.4e38f, zax = -3.4e38f;
#pragma unroll
        for (int s = 0; s < 10; s++) {
            lmax = fmaxf(lmax, l[s]);
            const float t  = -__logf(u[s]);
            const float zv = l[s] - __logf(t);
            za[s] = zv;
            if (u[s] <= 0.99f) zax = fmaxf(zax, zv);
        }
#pragma unroll
        for (int off = 16; off; off >>= 1) {
            lmax = fmaxf(lmax, __shfl_xor_sync(FULL, lmax, off));
            zax  = fmaxf(zax,  __shfl_xor_sync(FULL, zax,  off));
        }
        const float thresh = zax - 1e-3f;

        float zbest = -3.4e38f;
        int   ibest = 0x7fffffff;
#pragma unroll
        for (int jj = 0; jj < 5; jj++)
#pragma unroll
            for (int q = 0; q < 2; q++) {
                const int s = 2 * jj + q;
                if (u[s] > 0.99f || za[s] >= thresh) {
                    const float te = -acc_logf(u[s]);
                    const float zv = l[s] - acc_logf(te);
                    const int v = 64 * jj + 2 * lane + q;
                    if (zv > zbest || (zv == zbest && v < ibest)) { zbest = zv; ibest = v; }
                }
            }
#pragma unroll
        for (int off = 16; off; off >>= 1) {
            const float zo = __shfl_xor_sync(FULL, zbest, off);
            const int   io = __shfl_xor_sync(FULL, ibest, off);
            if (zo > zbest || (zo == zbest && io < ibest)) { zbest = zo; ibest = io; }
        }

        float e[10];
        float ssum = 0.0f;
#pragma unroll
        for (int s = 0; s < 10; s++) { e[s] = __expf(l[s] - lmax); ssum += e[s]; }
#pragma unroll
        for (int off = 16; off; off >>= 1)
            ssum += __shfl_xor_sync(FULL, ssum, off);
        const float rs = 1.0f / ssum;
#pragma unroll
        for (int s = 0; s < 10; s++) macc[g][s] = fmaf(e[s], rs, macc[g][s]);

        const float4* cvp = reinterpret_cast<const float4*>(
            codevectors + ((size_t)(g * VNUM + ibest)) * DDIM);
        float4* op = reinterpret_cast<float4*>(out + (size_t)n * 256 + g * DDIM);
        op[lane] = cvp[lane];
    }

#pragma unroll
    for (int g = 0; g < 2; g++)
#pragma unroll
        for (int jj = 0; jj < 5; jj++)
#pragma unroll
            for (int q = 0; q < 2; q++)
                atomicAdd(&smar[g * VNUM + 64 * jj + 2 * lane + q], macc[g][2 * jj + q]);
    __syncthreads();
    for (int i = tid; i < GVDIM; i += 256)
        atomicAdd(&g_marginal[i], smar[i]);
}

// ---------------------------------------------------------------------------
__global__ void perp_kernel(float* __restrict__ out, int out_size) {
    __shared__ float red[2];
    const int i    = threadIdx.x;          // 0..639
    const int lane = i & 31;
    if (i < 2) red[i] = 0.0f;
    __syncthreads();
    const float m = g_marginal[i] * (1.0f / (float)N_FRAMES);
    float part = m * acc_logf(m + 1e-7f);
#pragma unroll
    for (int off = 16; off; off >>= 1)
        part += __shfl_xor_sync(0xffffffffu, part, off);
    if (lane == 0) atomicAdd(&red[i >= VNUM ? 1 : 0], part);
    __syncthreads();
    if (i == 0) {
        const float perp = __expf(-red[0]) + __expf(-red[1]);
        if (out_size > N_FRAMES * 256) out[(size_t)N_FRAMES * 256] = perp;
    }
}

// ---------------------------------------------------------------------------
extern "C" void kernel_launch(void* const* d_in, const int* in_sizes, int n_in,
                              void* d_out, int out_size) {
    const float* hs = (const float*)d_in[0];   // [16,4096,512]
    const float* W  = (const float*)d_in[1];   // [512,640]
    const float* b  = (const float*)d_in[2];   // [640]
    const float* cv = (const float*)d_in[3];   // [640,128]
    const float* gu = (const float*)d_in[4];   // [131072,320]
    float* out = (float*)d_out;

    split_b_kernel<<<GVDIM, 512>>>(W);
    split_a_kernel<<<8192, 1024>>>(hs);

    cudaFuncSetAttribute(gemm_kernel,
                         cudaFuncAttributeMaxDynamicSharedMemorySize, SMEM_BYTES);
    gemm_kernel<<<dim3(5, 1024), 256, SMEM_BYTES>>>(b);

    epilogue_kernel<<<2048, 256>>>(gu, cv, out);
    perp_kernel<<<1, GVDIM>>>(out, out_size);
}

// round 13
// speedup vs baseline: 1.7937x; 1.7937x over previous
#include <cuda_runtime.h>
#include <cuda_fp16.h>
#include <cstdint>

#define N_FRAMES 65536
#define H_DIM    512
#define GVDIM    640
#define VNUM     320
#define DDIM     128

// --------------------------- device scratch --------------------------------
__device__ float g_logits[(size_t)N_FRAMES * GVDIM];   // 160 MiB (1-term approx)
__device__ float g_marginal[GVDIM];
__device__ __half g_A0[(size_t)N_FRAMES * H_DIM];      // 64 MiB  (hi split only)
__device__ __half g_B0[GVDIM * H_DIM];                 // W^T split hi [640][512]
__device__ __half g_B1[GVDIM * H_DIM];                 // W^T split lo (exact path)

// --------------------------- helpers ---------------------------------------
__device__ __forceinline__ uint32_t smem_u32(const void* p) {
    uint32_t a;
    asm("{ .reg .u64 t; cvta.to.shared.u64 t, %1; cvt.u32.u64 %0, t; }"
        : "=r"(a) : "l"(p));
    return a;
}

__device__ __forceinline__ void cp_async16(uint32_t saddr, const void* gaddr) {
    asm volatile("cp.async.cg.shared.global [%0], [%1], 16;"
                 :: "r"(saddr), "l"(gaddr) : "memory");
}

__device__ __forceinline__ void ldsm4(uint32_t r[4], uint32_t addr) {
    asm volatile("ldmatrix.sync.aligned.m8n8.x4.shared.b16 {%0,%1,%2,%3}, [%4];"
                 : "=r"(r[0]), "=r"(r[1]), "=r"(r[2]), "=r"(r[3]) : "r"(addr));
}

__device__ __forceinline__ void mma16816(float c[4], const uint32_t a[4],
                                         const uint32_t b[2]) {
    asm volatile(
        "mma.sync.aligned.m16n8k16.row.col.f32.f16.f16.f32 "
        "{%0,%1,%2,%3}, {%4,%5,%6,%7}, {%8,%9}, {%0,%1,%2,%3};"
        : "+f"(c[0]), "+f"(c[1]), "+f"(c[2]), "+f"(c[3])
        : "r"(a[0]), "r"(a[1]), "r"(a[2]), "r"(a[3]), "r"(b[0]), "r"(b[1]));
}

// ---------------------------------------------------------------------------
// ~1-ulp log (fast-math proof)
// ---------------------------------------------------------------------------
__device__ __forceinline__ float acc_logf(float x) {
    int   ix = __float_as_int(x);
    int   e  = ((ix >> 23) & 0xff) - 126;
    float m  = __int_as_float((ix & 0x007fffff) | 0x3f000000);
    if (m < 0.70710678118654752f) { m += m; e -= 1; }
    float f = m - 1.0f;
    float z = f * f;
    float p = 7.0376836292e-2f;
    p = fmaf(p, f, -1.1514610310e-1f);
    p = fmaf(p, f,  1.1676998740e-1f);
    p = fmaf(p, f, -1.2420140846e-1f);
    p = fmaf(p, f,  1.4249322787e-1f);
    p = fmaf(p, f, -1.6668057665e-1f);
    p = fmaf(p, f,  2.0000714765e-1f);
    p = fmaf(p, f, -2.4999993993e-1f);
    p = fmaf(p, f,  3.3333331174e-1f);
    p = p * f * z;
    float ef = (float)e;
    p = fmaf(-0.5f, z, p);
    float r = fmaf(ef, -2.12194440e-4f, p);
    r = r + f;
    r = fmaf(ef, 0.693359375f, r);
    return r;
}

// -log(u) for u in (0,1), accurate everywhere incl. u -> 1 (Sterbenz + series)
__device__ __forceinline__ float neg_log_acc(float u) {
    if (u > 0.99f) {
        const float t = 1.0f - u;   // exact
        return t * fmaf(t, fmaf(t, fmaf(t, 0.25f, 0.33333334f), 0.5f), 1.0f);
    }
    return -acc_logf(u);
}

// ---------------------------------------------------------------------------
// Splits
// ---------------------------------------------------------------------------
__global__ __launch_bounds__(1024) void split_a_kernel(const float* __restrict__ A) {
    size_t i = (size_t)blockIdx.x * blockDim.x + threadIdx.x;  // float4 index
    float4 x = reinterpret_cast<const float4*>(A)[i];
    __half2* p0 = reinterpret_cast<__half2*>(g_A0);
    p0[2 * i]     = __half2(__float2half_rn(x.x), __float2half_rn(x.y));
    p0[2 * i + 1] = __half2(__float2half_rn(x.z), __float2half_rn(x.w));
}

// W[k][n] -> B[n][k] hi/lo; also zeroes g_marginal
__global__ __launch_bounds__(512) void split_b_kernel(const float* __restrict__ W) {
    int n = blockIdx.x;
    int k = threadIdx.x;
    if (k == 0) g_marginal[n] = 0.0f;
    float v = W[(size_t)k * GVDIM + n];
    __half h0 = __float2half_rn(v);
    __half h1 = __float2half_rn(v - __half2float(h0));
    g_B0[(size_t)n * H_DIM + k] = h0;
    g_B1[(size_t)n * H_DIM + k] = h1;
}

// ---------------------------------------------------------------------------
// GEMM (1 term): logits1 = A0*B0 + b.
// BM=128, BN=128, BK=32; 256 threads; 8 warps (2x4), warp tile 64x32.
// Double-buffered smem, 80B padded rows, ONE sync per stage.
// ---------------------------------------------------------------------------
#define STG_BYTES   20480          // A(10240) + B(10240)
#define SMEM_BYTES  (2 * STG_BYTES)

__global__ __launch_bounds__(256, 2) void gemm_kernel(const float* __restrict__ bias) {
    extern __shared__ char smem[];
    const uint32_t sb = smem_u32(smem);
    const int tid  = threadIdx.x;
    const int wid  = tid >> 5;
    const int lane = tid & 31;
    const int wm = wid >> 2;
    const int wn = wid & 3;
    const int m0 = blockIdx.y * 128;
    const int n0 = blockIdx.x * 128;

    float acc[4][4][4];
#pragma unroll
    for (int mf = 0; mf < 4; mf++)
#pragma unroll
        for (int nf = 0; nf < 4; nf++)
#pragma unroll
            for (int c = 0; c < 4; c++) acc[mf][nf][c] = 0.0f;

    const int r0 = tid >> 2;
    const int kc = tid & 3;
    const __half* pA0 = g_A0 + (size_t)(m0 + r0) * H_DIM + kc * 8;
    const __half* pB0 = g_B0 + (size_t)(n0 + r0) * H_DIM + kc * 8;
    const uint32_t sA = sb + r0 * 80 + kc * 16;
    const size_t ROW64 = (size_t)64 * H_DIM;

    auto issue_stage = [&](int s) {
        const int off = s * 32;
        const uint32_t buf = (uint32_t)(s & 1) * STG_BYTES;
        cp_async16(sA + buf,                 pA0 + off);
        cp_async16(sA + buf + 5120,          pA0 + off + ROW64);
        cp_async16(sA + buf + 10240,         pB0 + off);
        cp_async16(sA + buf + 10240 + 5120,  pB0 + off + ROW64);
        asm volatile("cp.async.commit_group;" ::: "memory");
    };

    issue_stage(0);

    const int a_row = wm * 64 + (lane & 15);
    const int a_kc  = (lane >> 4) * 16;
    const int b_row = wn * 32 + ((lane >> 4) & 1) * 8 + (lane & 7);
    const int b_kc  = ((lane >> 3) & 1) * 16;

    for (int s = 0; s < 16; s++) {
        asm volatile("cp.async.wait_group 0;" ::: "memory");
        __syncthreads();
        if (s + 1 < 16) issue_stage(s + 1);

        const uint32_t abase = sb + (s & 1) * STG_BYTES;
        const uint32_t bbase = abase + 10240;

#pragma unroll
        for (int ks = 0; ks < 2; ks++) {
            uint32_t Bf[8];
#pragma unroll
            for (int p = 0; p < 2; p++)
                ldsm4(&Bf[p * 4], bbase + (b_row + p * 16) * 80 + ks * 32 + b_kc);

            uint32_t Af[4][4];
#pragma unroll
            for (int mf = 0; mf < 4; mf++)
                ldsm4(Af[mf], abase + (a_row + mf * 16) * 80 + ks * 32 + a_kc);
#pragma unroll
            for (int mf = 0; mf < 4; mf++)
#pragma unroll
                for (int nf = 0; nf < 4; nf++)
                    mma16816(acc[mf][nf], Af[mf], &Bf[nf * 2]);
        }
    }

    const int gID = lane >> 2;
    const int tig = lane & 3;
    float2 bv[4];
#pragma unroll
    for (int nf = 0; nf < 4; nf++)
        bv[nf] = *reinterpret_cast<const float2*>(bias + n0 + wn * 32 + nf * 8 + tig * 2);

#pragma unroll
    for (int mf = 0; mf < 4; mf++) {
        const int m = m0 + wm * 64 + mf * 16 + gID;
#pragma unroll
        for (int nf = 0; nf < 4; nf++) {
            const int n = n0 + wn * 32 + nf * 8 + tig * 2;
            float2 v0 = {acc[mf][nf][0] + bv[nf].x, acc[mf][nf][1] + bv[nf].y};
            float2 v1 = {acc[mf][nf][2] + bv[nf].x, acc[mf][nf][3] + bv[nf].y};
            *reinterpret_cast<float2*>(g_logits + (size_t)m * GVDIM + n)       = v0;
            *reinterpret_cast<float2*>(g_logits + (size_t)(m + 8) * GVDIM + n) = v1;
        }
    }
}

// ---------------------------------------------------------------------------
// Exact logit: fp32 A row . (B0+B1) column, warp-collective.
// ---------------------------------------------------------------------------
__device__ float warp_dot(const float* __restrict__ arow,
                          const __half* __restrict__ b0row,
                          const __half* __restrict__ b1row, int lane) {
    const unsigned FULL = 0xffffffffu;
    float s = 0.0f;
    const float4*   a4  = reinterpret_cast<const float4*>(arow) + lane * 4;
    const __half2*  b02 = reinterpret_cast<const __half2*>(b0row) + lane * 8;
    const __half2*  b12 = reinterpret_cast<const __half2*>(b1row) + lane * 8;
#pragma unroll
    for (int i = 0; i < 4; i++) {
        float4 a  = a4[i];
        float2 p0 = __half22float2(b02[2 * i]);
        float2 q0 = __half22float2(b12[2 * i]);
        float2 p1 = __half22float2(b02[2 * i + 1]);
        float2 q1 = __half22float2(b12[2 * i + 1]);
        s = fmaf(a.x, p0.x + q0.x, s);
        s = fmaf(a.y, p0.y + q0.y, s);
        s = fmaf(a.z, p1.x + q1.x, s);
        s = fmaf(a.w, p1.y + q1.y, s);
    }
#pragma unroll
    for (int off = 16; off; off >>= 1)
        s += __shfl_xor_sync(FULL, s, off);
    return s;
}

// ---------------------------------------------------------------------------
// Epilogue: one warp per (n,g) pair; 8 pairs/warp; 2048 blocks x 256 thr.
// Approx z from 1-term logits (reliable log via select); margin 3e-3.
// Single candidate (99.7% of rows) -> done. Else exact fp32 dots (rare).
// ---------------------------------------------------------------------------
__global__ __launch_bounds__(256) void epilogue_kernel(
    const float* __restrict__ A,
    const float* __restrict__ bias,
    const float* __restrict__ gumbel_u,
    const float* __restrict__ codevectors,
    float* __restrict__ out)
{
    const unsigned FULL = 0xffffffffu;
    __shared__ float smar[GVDIM];
    const int tid  = threadIdx.x;
    const int warp = blockIdx.x * 8 + (tid >> 5);
    const int lane = tid & 31;

    for (int i = tid; i < GVDIM; i += 256) smar[i] = 0.0f;
    __syncthreads();

    float macc[2][10];
#pragma unroll
    for (int g = 0; g < 2; g++)
#pragma unroll
        for (int j = 0; j < 10; j++) macc[g][j] = 0.0f;

    const int p0 = warp * 8;
    for (int i = 0; i < 8; i++) {
        const int p = p0 + i;
        const int n = p >> 1;
        const int g = p & 1;
        const float* lrow = g_logits + (size_t)n * GVDIM + g * VNUM;
        const float* urow = gumbel_u + (size_t)p * VNUM;

        float l[10], u[10], za[10];
#pragma unroll
        for (int jj = 0; jj < 5; jj++) {
            const int e0 = 2 * (lane + 32 * jj);
            float2 lf = *reinterpret_cast<const float2*>(lrow + e0);
            float2 uf = *reinterpret_cast<const float2*>(urow + e0);
            l[2 * jj] = lf.x; l[2 * jj + 1] = lf.y;
            u[2 * jj] = uf.x; u[2 * jj + 1] = uf.y;
        }

        // ---- approx pass, reliable for all u ----
        float lmax = -3.4e38f, zax = -3.4e38f;
#pragma unroll
        for (int s = 0; s < 10; s++) {
            lmax = fmaxf(lmax, l[s]);
            const float t1 = 1.0f - u[s];
            const float ws = t1 * fmaf(t1, fmaf(t1, 0.33333334f, 0.5f), 1.0f);
            const float wm = -__logf(u[s]);
            const float w  = (u[s] > 0.99f) ? ws : wm;
            za[s] = l[s] - __logf(w);
            zax = fmaxf(zax, za[s]);
        }
#pragma unroll
        for (int off = 16; off; off >>= 1) {
            lmax = fmaxf(lmax, __shfl_xor_sync(FULL, lmax, off));
            zax  = fmaxf(zax,  __shfl_xor_sync(FULL, zax,  off));
        }
        const float thresh = zax - 3e-3f;

        // ---- candidate ballots ----
        unsigned bal[10];
        int total = 0;
#pragma unroll
        for (int s = 0; s < 10; s++) {
            bal[s] = __ballot_sync(FULL, za[s] >= thresh);
            total += __popc(bal[s]);
        }

        int ibest;
        if (total == 1) {
            ibest = 0;
#pragma unroll
            for (int s = 0; s < 10; s++)
                if (bal[s]) {
                    const int ln = __ffs(bal[s]) - 1;
                    ibest = 64 * (s >> 1) + 2 * ln + (s & 1);
                }
        } else {
            // rare: exact fp32 recompute of all candidates
            float zb = -3.4e38f;
            int   ib = 0x7fffffff;
            const float*  arow = A + (size_t)n * H_DIM;
            const __half* b0b  = g_B0 + (size_t)(g * VNUM) * H_DIM;
            const __half* b1b  = g_B1 + (size_t)(g * VNUM) * H_DIM;
#pragma unroll
            for (int s = 0; s < 10; s++) {
                unsigned m = bal[s];
                while (m) {
                    const int ln = __ffs(m) - 1; m &= m - 1;
                    const int v  = 64 * (s >> 1) + 2 * ln + (s & 1);
                    const float uc = __shfl_sync(FULL, u[s], ln);
                    const float dot = warp_dot(arow, b0b + (size_t)v * H_DIM,
                                               b1b + (size_t)v * H_DIM, lane);
                    const float w = neg_log_acc(uc);
                    const float z = dot + bias[g * VNUM + v] - acc_logf(w);
                    if (z > zb || (z == zb && v < ib)) { zb = z; ib = v; }
                }
            }
            ibest = ib;
        }

        // ---- noise-free softmax -> marginal partials (1-term logits) ----
        float e[10];
        float ssum = 0.0f;
#pragma unroll
        for (int s = 0; s < 10; s++) { e[s] = __expf(l[s] - lmax); ssum += e[s]; }
#pragma unroll
        for (int off = 16; off; off >>= 1)
            ssum += __shfl_xor_sync(FULL, ssum, off);
        const float rs = 1.0f / ssum;
#pragma unroll
        for (int s = 0; s < 10; s++) macc[g][s] = fmaf(e[s], rs, macc[g][s]);

        // ---- codes gather ----
        const float4* cvp = reinterpret_cast<const float4*>(
            codevectors + ((size_t)(g * VNUM + ibest)) * DDIM);
        float4* op = reinterpret_cast<float4*>(out + (size_t)n * 256 + g * DDIM);
        op[lane] = cvp[lane];
    }

#pragma unroll
    for (int g = 0; g < 2; g++)
#pragma unroll
        for (int jj = 0; jj < 5; jj++)
#pragma unroll
            for (int q = 0; q < 2; q++)
                atomicAdd(&smar[g * VNUM + 64 * jj + 2 * lane + q], macc[g][2 * jj + q]);
    __syncthreads();
    for (int i = tid; i < GVDIM; i += 256)
        atomicAdd(&g_marginal[i], smar[i]);
}

// ---------------------------------------------------------------------------
__global__ void perp_kernel(float* __restrict__ out, int out_size) {
    __shared__ float red[2];
    const int i    = threadIdx.x;          // 0..639
    const int lane = i & 31;
    if (i < 2) red[i] = 0.0f;
    __syncthreads();
    const float m = g_marginal[i] * (1.0f / (float)N_FRAMES);
    float part = m * acc_logf(m + 1e-7f);
#pragma unroll
    for (int off = 16; off; off >>= 1)
        part += __shfl_xor_sync(0xffffffffu, part, off);
    if (lane == 0) atomicAdd(&red[i >= VNUM ? 1 : 0], part);
    __syncthreads();
    if (i == 0) {
        const float perp = __expf(-red[0]) + __expf(-red[1]);
        if (out_size > N_FRAMES * 256) out[(size_t)N_FRAMES * 256] = perp;
    }
}

// ---------------------------------------------------------------------------
extern "C" void kernel_launch(void* const* d_in, const int* in_sizes, int n_in,
                              void* d_out, int out_size) {
    const float* hs = (const float*)d_in[0];   // [16,4096,512]
    const float* W  = (const float*)d_in[1];   // [512,640]
    const float* b  = (const float*)d_in[2];   // [640]
    const float* cv = (const float*)d_in[3];   // [640,128]
    const float* gu = (const float*)d_in[4];   // [131072,320]
    float* out = (float*)d_out;

    split_b_kernel<<<GVDIM, 512>>>(W);
    split_a_kernel<<<8192, 1024>>>(hs);

    cudaFuncSetAttribute(gemm_kernel,
                         cudaFuncAttributeMaxDynamicSharedMemorySize, SMEM_BYTES);
    gemm_kernel<<<dim3(5, 512), 256, SMEM_BYTES>>>(b);

    epilogue_kernel<<<2048, 256>>>(hs, b, gu, cv, out);
    perp_kernel<<<1, GVDIM>>>(out, out_size);
}

// round 14
// speedup vs baseline: 1.8166x; 1.0128x over previous
#include <cuda_runtime.h>
#include <cuda_fp16.h>
#include <cstdint>

#define N_FRAMES 65536
#define H_DIM    512
#define GVDIM    640
#define VNUM     320
#define DDIM     128

// --------------------------- device scratch --------------------------------
__device__ __half g_logits[(size_t)N_FRAMES * GVDIM];  // 80 MiB (1-term, fp16)
__device__ float g_marginal[GVDIM];
__device__ __half g_A0[(size_t)N_FRAMES * H_DIM];      // 64 MiB  (hi split only)
__device__ __half g_B0[GVDIM * H_DIM];                 // W^T split hi [640][512]
__device__ __half g_B1[GVDIM * H_DIM];                 // W^T split lo (exact path)

// --------------------------- helpers ---------------------------------------
__device__ __forceinline__ uint32_t smem_u32(const void* p) {
    uint32_t a;
    asm("{ .reg .u64 t; cvta.to.shared.u64 t, %1; cvt.u32.u64 %0, t; }"
        : "=r"(a) : "l"(p));
    return a;
}

__device__ __forceinline__ void cp_async16(uint32_t saddr, const void* gaddr) {
    asm volatile("cp.async.cg.shared.global [%0], [%1], 16;"
                 :: "r"(saddr), "l"(gaddr) : "memory");
}

__device__ __forceinline__ void ldsm4(uint32_t r[4], uint32_t addr) {
    asm volatile("ldmatrix.sync.aligned.m8n8.x4.shared.b16 {%0,%1,%2,%3}, [%4];"
                 : "=r"(r[0]), "=r"(r[1]), "=r"(r[2]), "=r"(r[3]) : "r"(addr));
}

__device__ __forceinline__ void mma16816(float c[4], const uint32_t a[4],
                                         const uint32_t b[2]) {
    asm volatile(
        "mma.sync.aligned.m16n8k16.row.col.f32.f16.f16.f32 "
        "{%0,%1,%2,%3}, {%4,%5,%6,%7}, {%8,%9}, {%0,%1,%2,%3};"
        : "+f"(c[0]), "+f"(c[1]), "+f"(c[2]), "+f"(c[3])
        : "r"(a[0]), "r"(a[1]), "r"(a[2]), "r"(a[3]), "r"(b[0]), "r"(b[1]));
}

// ---------------------------------------------------------------------------
// ~1-ulp log (fast-math proof)
// ---------------------------------------------------------------------------
__device__ __forceinline__ float acc_logf(float x) {
    int   ix = __float_as_int(x);
    int   e  = ((ix >> 23) & 0xff) - 126;
    float m  = __int_as_float((ix & 0x007fffff) | 0x3f000000);
    if (m < 0.70710678118654752f) { m += m; e -= 1; }
    float f = m - 1.0f;
    float z = f * f;
    float p = 7.0376836292e-2f;
    p = fmaf(p, f, -1.1514610310e-1f);
    p = fmaf(p, f,  1.1676998740e-1f);
    p = fmaf(p, f, -1.2420140846e-1f);
    p = fmaf(p, f,  1.4249322787e-1f);
    p = fmaf(p, f, -1.6668057665e-1f);
    p = fmaf(p, f,  2.0000714765e-1f);
    p = fmaf(p, f, -2.4999993993e-1f);
    p = fmaf(p, f,  3.3333331174e-1f);
    p = p * f * z;
    float ef = (float)e;
    p = fmaf(-0.5f, z, p);
    float r = fmaf(ef, -2.12194440e-4f, p);
    r = r + f;
    r = fmaf(ef, 0.693359375f, r);
    return r;
}

// -log(u) for u in (0,1), accurate everywhere incl. u -> 1 (Sterbenz + series)
__device__ __forceinline__ float neg_log_acc(float u) {
    if (u > 0.99f) {
        const float t = 1.0f - u;   // exact
        return t * fmaf(t, fmaf(t, fmaf(t, 0.25f, 0.33333334f), 0.5f), 1.0f);
    }
    return -acc_logf(u);
}

// ---------------------------------------------------------------------------
// Splits
// ---------------------------------------------------------------------------
__global__ __launch_bounds__(1024) void split_a_kernel(const float* __restrict__ A) {
    size_t i = (size_t)blockIdx.x * blockDim.x + threadIdx.x;  // float4 index
    float4 x = reinterpret_cast<const float4*>(A)[i];
    __half2* p0 = reinterpret_cast<__half2*>(g_A0);
    p0[2 * i]     = __half2(__float2half_rn(x.x), __float2half_rn(x.y));
    p0[2 * i + 1] = __half2(__float2half_rn(x.z), __float2half_rn(x.w));
}

// W[k][n] -> B[n][k] hi/lo; also zeroes g_marginal
__global__ __launch_bounds__(512) void split_b_kernel(const float* __restrict__ W) {
    int n = blockIdx.x;
    int k = threadIdx.x;
    if (k == 0) g_marginal[n] = 0.0f;
    float v = W[(size_t)k * GVDIM + n];
    __half h0 = __float2half_rn(v);
    __half h1 = __float2half_rn(v - __half2float(h0));
    g_B0[(size_t)n * H_DIM + k] = h0;
    g_B1[(size_t)n * H_DIM + k] = h1;
}

// ---------------------------------------------------------------------------
// GEMM (1 term): logits16 = fp16(A0*B0 + b).
// BM=128, BN=128, BK=32; 256 threads; 8 warps (2x4), warp tile 64x32.
// Double-buffered smem, 80B padded rows, ONE sync per stage.
// ---------------------------------------------------------------------------
#define STG_BYTES   20480          // A(10240) + B(10240)
#define SMEM_BYTES  (2 * STG_BYTES)

__global__ __launch_bounds__(256, 2) void gemm_kernel(const float* __restrict__ bias) {
    extern __shared__ char smem[];
    const uint32_t sb = smem_u32(smem);
    const int tid  = threadIdx.x;
    const int wid  = tid >> 5;
    const int lane = tid & 31;
    const int wm = wid >> 2;
    const int wn = wid & 3;
    const int m0 = blockIdx.y * 128;
    const int n0 = blockIdx.x * 128;

    float acc[4][4][4];
#pragma unroll
    for (int mf = 0; mf < 4; mf++)
#pragma unroll
        for (int nf = 0; nf < 4; nf++)
#pragma unroll
            for (int c = 0; c < 4; c++) acc[mf][nf][c] = 0.0f;

    const int r0 = tid >> 2;
    const int kc = tid & 3;
    const __half* pA0 = g_A0 + (size_t)(m0 + r0) * H_DIM + kc * 8;
    const __half* pB0 = g_B0 + (size_t)(n0 + r0) * H_DIM + kc * 8;
    const uint32_t sA = sb + r0 * 80 + kc * 16;
    const size_t ROW64 = (size_t)64 * H_DIM;

    auto issue_stage = [&](int s) {
        const int off = s * 32;
        const uint32_t buf = (uint32_t)(s & 1) * STG_BYTES;
        cp_async16(sA + buf,                 pA0 + off);
        cp_async16(sA + buf + 5120,          pA0 + off + ROW64);
        cp_async16(sA + buf + 10240,         pB0 + off);
        cp_async16(sA + buf + 10240 + 5120,  pB0 + off + ROW64);
        asm volatile("cp.async.commit_group;" ::: "memory");
    };

    issue_stage(0);

    const int a_row = wm * 64 + (lane & 15);
    const int a_kc  = (lane >> 4) * 16;
    const int b_row = wn * 32 + ((lane >> 4) & 1) * 8 + (lane & 7);
    const int b_kc  = ((lane >> 3) & 1) * 16;

    for (int s = 0; s < 16; s++) {
        asm volatile("cp.async.wait_group 0;" ::: "memory");
        __syncthreads();
        if (s + 1 < 16) issue_stage(s + 1);

        const uint32_t abase = sb + (s & 1) * STG_BYTES;
        const uint32_t bbase = abase + 10240;

#pragma unroll
        for (int ks = 0; ks < 2; ks++) {
            uint32_t Bf[8];
#pragma unroll
            for (int p = 0; p < 2; p++)
                ldsm4(&Bf[p * 4], bbase + (b_row + p * 16) * 80 + ks * 32 + b_kc);

            uint32_t Af[4][4];
#pragma unroll
            for (int mf = 0; mf < 4; mf++)
                ldsm4(Af[mf], abase + (a_row + mf * 16) * 80 + ks * 32 + a_kc);
#pragma unroll
            for (int mf = 0; mf < 4; mf++)
#pragma unroll
                for (int nf = 0; nf < 4; nf++)
                    mma16816(acc[mf][nf], Af[mf], &Bf[nf * 2]);
        }
    }

    const int gID = lane >> 2;
    const int tig = lane & 3;
    float2 bv[4];
#pragma unroll
    for (int nf = 0; nf < 4; nf++)
        bv[nf] = *reinterpret_cast<const float2*>(bias + n0 + wn * 32 + nf * 8 + tig * 2);

#pragma unroll
    for (int mf = 0; mf < 4; mf++) {
        const int m = m0 + wm * 64 + mf * 16 + gID;
#pragma unroll
        for (int nf = 0; nf < 4; nf++) {
            const int n = n0 + wn * 32 + nf * 8 + tig * 2;
            __half2 h0 = __floats2half2_rn(acc[mf][nf][0] + bv[nf].x,
                                           acc[mf][nf][1] + bv[nf].y);
            __half2 h1 = __floats2half2_rn(acc[mf][nf][2] + bv[nf].x,
                                           acc[mf][nf][3] + bv[nf].y);
            *reinterpret_cast<__half2*>(g_logits + (size_t)m * GVDIM + n)       = h0;
            *reinterpret_cast<__half2*>(g_logits + (size_t)(m + 8) * GVDIM + n) = h1;
        }
    }
}

// ---------------------------------------------------------------------------
// Exact logit: fp32 A row . (B0+B1) column, warp-collective.
// ---------------------------------------------------------------------------
__device__ float warp_dot(const float* __restrict__ arow,
                          const __half* __restrict__ b0row,
                          const __half* __restrict__ b1row, int lane) {
    const unsigned FULL = 0xffffffffu;
    float s = 0.0f;
    const float4*   a4  = reinterpret_cast<const float4*>(arow) + lane * 4;
    const __half2*  b02 = reinterpret_cast<const __half2*>(b0row) + lane * 8;
    const __half2*  b12 = reinterpret_cast<const __half2*>(b1row) + lane * 8;
#pragma unroll
    for (int i = 0; i < 4; i++) {
        float4 a  = a4[i];
        float2 p0 = __half22float2(b02[2 * i]);
        float2 q0 = __half22float2(b12[2 * i]);
        float2 p1 = __half22float2(b02[2 * i + 1]);
        float2 q1 = __half22float2(b12[2 * i + 1]);
        s = fmaf(a.x, p0.x + q0.x, s);
        s = fmaf(a.y, p0.y + q0.y, s);
        s = fmaf(a.z, p1.x + q1.x, s);
        s = fmaf(a.w, p1.y + q1.y, s);
    }
#pragma unroll
    for (int off = 16; off; off >>= 1)
        s += __shfl_xor_sync(FULL, s, off);
    return s;
}

// ---------------------------------------------------------------------------
// Epilogue: one warp per (n,g) pair; 8 pairs/warp; 2048 blocks x 256 thr.
// Approx z from fp16 1-term logits; margin 1e-2 covers quantization+log err.
// Single candidate (~99% of rows) -> done. Else exact fp32 dots (rare).
// ---------------------------------------------------------------------------
__global__ __launch_bounds__(256) void epilogue_kernel(
    const float* __restrict__ A,
    const float* __restrict__ bias,
    const float* __restrict__ gumbel_u,
    const float* __restrict__ codevectors,
    float* __restrict__ out)
{
    const unsigned FULL = 0xffffffffu;
    __shared__ float smar[GVDIM];
    const int tid  = threadIdx.x;
    const int warp = blockIdx.x * 8 + (tid >> 5);
    const int lane = tid & 31;

    for (int i = tid; i < GVDIM; i += 256) smar[i] = 0.0f;
    __syncthreads();

    float macc[2][10];
#pragma unroll
    for (int g = 0; g < 2; g++)
#pragma unroll
        for (int j = 0; j < 10; j++) macc[g][j] = 0.0f;

    const int p0 = warp * 8;
    for (int i = 0; i < 8; i++) {
        const int p = p0 + i;
        const int n = p >> 1;
        const int g = p & 1;
        const __half* lrow = g_logits + (size_t)n * GVDIM + g * VNUM;
        const float*  urow = gumbel_u + (size_t)p * VNUM;

        float l[10], u[10], za[10];
#pragma unroll
        for (int jj = 0; jj < 5; jj++) {
            const __half2 lh = *reinterpret_cast<const __half2*>(lrow + 2 * (lane + 32 * jj));
            float2 lf = __half22float2(lh);
            float2 uf = *reinterpret_cast<const float2*>(urow + 2 * (lane + 32 * jj));
            l[2 * jj] = lf.x; l[2 * jj + 1] = lf.y;
            u[2 * jj] = uf.x; u[2 * jj + 1] = uf.y;
        }

        // ---- approx pass, reliable for all u ----
        float lmax = -3.4e38f, zax = -3.4e38f;
#pragma unroll
        for (int s = 0; s < 10; s++) {
            lmax = fmaxf(lmax, l[s]);
            const float t1 = 1.0f - u[s];
            const float ws = t1 * fmaf(t1, fmaf(t1, 0.33333334f, 0.5f), 1.0f);
            const float wm = -__logf(u[s]);
            const float w  = (u[s] > 0.99f) ? ws : wm;
            za[s] = l[s] - __logf(w);
            zax = fmaxf(zax, za[s]);
        }
#pragma unroll
        for (int off = 16; off; off >>= 1) {
            lmax = fmaxf(lmax, __shfl_xor_sync(FULL, lmax, off));
            zax  = fmaxf(zax,  __shfl_xor_sync(FULL, zax,  off));
        }
        const float thresh = zax - 1e-2f;

        // ---- candidate ballots ----
        unsigned bal[10];
        int total = 0;
#pragma unroll
        for (int s = 0; s < 10; s++) {
            bal[s] = __ballot_sync(FULL, za[s] >= thresh);
            total += __popc(bal[s]);
        }

        int ibest;
        if (total == 1) {
            ibest = 0;
#pragma unroll
            for (int s = 0; s < 10; s++)
                if (bal[s]) {
                    const int ln = __ffs(bal[s]) - 1;
                    ibest = 64 * (s >> 1) + 2 * ln + (s & 1);
                }
        } else {
            // rare: exact fp32 recompute of all candidates
            float zb = -3.4e38f;
            int   ib = 0x7fffffff;
            const float*  arow = A + (size_t)n * H_DIM;
            const __half* b0b  = g_B0 + (size_t)(g * VNUM) * H_DIM;
            const __half* b1b  = g_B1 + (size_t)(g * VNUM) * H_DIM;
#pragma unroll
            for (int s = 0; s < 10; s++) {
                unsigned m = bal[s];
                while (m) {
                    const int ln = __ffs(m) - 1; m &= m - 1;
                    const int v  = 64 * (s >> 1) + 2 * ln + (s & 1);
                    const float uc = __shfl_sync(FULL, u[s], ln);
                    const float dot = warp_dot(arow, b0b + (size_t)v * H_DIM,
                                               b1b + (size_t)v * H_DIM, lane);
                    const float w = neg_log_acc(uc);
                    const float z = dot + bias[g * VNUM + v] - acc_logf(w);
                    if (z > zb || (z == zb && v < ib)) { zb = z; ib = v; }
                }
            }
            ibest = ib;
        }

        // ---- noise-free softmax -> marginal partials (fp16 logits) ----
        float e[10];
        float ssum = 0.0f;
#pragma unroll
        for (int s = 0; s < 10; s++) { e[s] = __expf(l[s] - lmax); ssum += e[s]; }
#pragma unroll
        for (int off = 16; off; off >>= 1)
            ssum += __shfl_xor_sync(FULL, ssum, off);
        const float rs = 1.0f / ssum;
#pragma unroll
        for (int s = 0; s < 10; s++) macc[g][s] = fmaf(e[s], rs, macc[g][s]);

        // ---- codes gather ----
        const float4* cvp = reinterpret_cast<const float4*>(
            codevectors + ((size_t)(g * VNUM + ibest)) * DDIM);
        float4* op = reinterpret_cast<float4*>(out + (size_t)n * 256 + g * DDIM);
        op[lane] = cvp[lane];
    }

#pragma unroll
    for (int g = 0; g < 2; g++)
#pragma unroll
        for (int jj = 0; jj < 5; jj++)
#pragma unroll
            for (int q = 0; q < 2; q++)
                atomicAdd(&smar[g * VNUM + 64 * jj + 2 * lane + q], macc[g][2 * jj + q]);
    __syncthreads();
    for (int i = tid; i < GVDIM; i += 256)
        atomicAdd(&g_marginal[i], smar[i]);
}

// ---------------------------------------------------------------------------
__global__ void perp_kernel(float* __restrict__ out, int out_size) {
    __shared__ float red[2];
    const int i    = threadIdx.x;          // 0..639
    const int lane = i & 31;
    if (i < 2) red[i] = 0.0f;
    __syncthreads();
    const float m = g_marginal[i] * (1.0f / (float)N_FRAMES);
    float part = m * acc_logf(m + 1e-7f);
#pragma unroll
    for (int off = 16; off; off >>= 1)
        part += __shfl_xor_sync(0xffffffffu, part, off);
    if (lane == 0) atomicAdd(&red[i >= VNUM ? 1 : 0], part);
    __syncthreads();
    if (i == 0) {
        const float perp = __expf(-red[0]) + __expf(-red[1]);
        if (out_size > N_FRAMES * 256) out[(size_t)N_FRAMES * 256] = perp;
    }
}

// ---------------------------------------------------------------------------
extern "C" void kernel_launch(void* const* d_in, const int* in_sizes, int n_in,
                              void* d_out, int out_size) {
    const float* hs = (const float*)d_in[0];   // [16,4096,512]
    const float* W  = (const float*)d_in[1];   // [512,640]
    const float* b  = (const float*)d_in[2];   // [640]
    const float* cv = (const float*)d_in[3];   // [640,128]
    const float* gu = (const float*)d_in[4];   // [131072,320]
    float* out = (float*)d_out;

    split_b_kernel<<<GVDIM, 512>>>(W);
    split_a_kernel<<<8192, 1024>>>(hs);

    cudaFuncSetAttribute(gemm_kernel,
                         cudaFuncAttributeMaxDynamicSharedMemorySize, SMEM_BYTES);
    gemm_kernel<<<dim3(5, 512), 256, SMEM_BYTES>>>(b);

    epilogue_kernel<<<2048, 256>>>(hs, b, gu, cv, out);
    perp_kernel<<<1, GVDIM>>>(out, out_size);
}

// round 15
// speedup vs baseline: 1.8569x; 1.0222x over previous
#include <cuda_runtime.h>
#include <cuda_fp16.h>
#include <cstdint>

#define N_FRAMES 65536
#define H_DIM    512
#define GVDIM    640
#define VNUM     320
#define DDIM     128

// --------------------------- device scratch --------------------------------
__device__ __half g_logits[(size_t)N_FRAMES * GVDIM];  // 80 MiB (1-term, fp16)
__device__ float g_marginal[GVDIM];
__device__ __half g_A0[(size_t)N_FRAMES * H_DIM];      // 64 MiB  (hi split only)
__device__ __half g_B0[GVDIM * H_DIM];                 // W^T split hi [640][512]
__device__ __half g_B1[GVDIM * H_DIM];                 // W^T split lo (exact path)

// --------------------------- helpers ---------------------------------------
__device__ __forceinline__ uint32_t smem_u32(const void* p) {
    uint32_t a;
    asm("{ .reg .u64 t; cvta.to.shared.u64 t, %1; cvt.u32.u64 %0, t; }"
        : "=r"(a) : "l"(p));
    return a;
}

__device__ __forceinline__ void cp_async16(uint32_t saddr, const void* gaddr) {
    asm volatile("cp.async.cg.shared.global [%0], [%1], 16;"
                 :: "r"(saddr), "l"(gaddr) : "memory");
}

__device__ __forceinline__ void ldsm4(uint32_t r[4], uint32_t addr) {
    asm volatile("ldmatrix.sync.aligned.m8n8.x4.shared.b16 {%0,%1,%2,%3}, [%4];"
                 : "=r"(r[0]), "=r"(r[1]), "=r"(r[2]), "=r"(r[3]) : "r"(addr));
}

__device__ __forceinline__ void mma16816(float c[4], const uint32_t a[4],
                                         const uint32_t b[2]) {
    asm volatile(
        "mma.sync.aligned.m16n8k16.row.col.f32.f16.f16.f32 "
        "{%0,%1,%2,%3}, {%4,%5,%6,%7}, {%8,%9}, {%0,%1,%2,%3};"
        : "+f"(c[0]), "+f"(c[1]), "+f"(c[2]), "+f"(c[3])
        : "r"(a[0]), "r"(a[1]), "r"(a[2]), "r"(a[3]), "r"(b[0]), "r"(b[1]));
}

// ---------------------------------------------------------------------------
// ~1-ulp log (fast-math proof)
// ---------------------------------------------------------------------------
__device__ __forceinline__ float acc_logf(float x) {
    int   ix = __float_as_int(x);
    int   e  = ((ix >> 23) & 0xff) - 126;
    float m  = __int_as_float((ix & 0x007fffff) | 0x3f000000);
    if (m < 0.70710678118654752f) { m += m; e -= 1; }
    float f = m - 1.0f;
    float z = f * f;
    float p = 7.0376836292e-2f;
    p = fmaf(p, f, -1.1514610310e-1f);
    p = fmaf(p, f,  1.1676998740e-1f);
    p = fmaf(p, f, -1.2420140846e-1f);
    p = fmaf(p, f,  1.4249322787e-1f);
    p = fmaf(p, f, -1.6668057665e-1f);
    p = fmaf(p, f,  2.0000714765e-1f);
    p = fmaf(p, f, -2.4999993993e-1f);
    p = fmaf(p, f,  3.3333331174e-1f);
    p = p * f * z;
    float ef = (float)e;
    p = fmaf(-0.5f, z, p);
    float r = fmaf(ef, -2.12194440e-4f, p);
    r = r + f;
    r = fmaf(ef, 0.693359375f, r);
    return r;
}

// -log(u) for u in (0,1), accurate everywhere incl. u -> 1 (Sterbenz + series)
__device__ __forceinline__ float neg_log_acc(float u) {
    if (u > 0.99f) {
        const float t = 1.0f - u;   // exact
        return t * fmaf(t, fmaf(t, fmaf(t, 0.25f, 0.33333334f), 0.5f), 1.0f);
    }
    return -acc_logf(u);
}

// ---------------------------------------------------------------------------
// Splits
// ---------------------------------------------------------------------------
__global__ __launch_bounds__(1024) void split_a_kernel(const float* __restrict__ A) {
    size_t i = (size_t)blockIdx.x * blockDim.x + threadIdx.x;  // float4 index
    float4 x = reinterpret_cast<const float4*>(A)[i];
    __half2* p0 = reinterpret_cast<__half2*>(g_A0);
    p0[2 * i]     = __half2(__float2half_rn(x.x), __float2half_rn(x.y));
    p0[2 * i + 1] = __half2(__float2half_rn(x.z), __float2half_rn(x.w));
}

// W[k][n] -> B[n][k] hi/lo; also zeroes g_marginal
__global__ __launch_bounds__(512) void split_b_kernel(const float* __restrict__ W) {
    int n = blockIdx.x;
    int k = threadIdx.x;
    if (k == 0) g_marginal[n] = 0.0f;
    float v = W[(size_t)k * GVDIM + n];
    __half h0 = __float2half_rn(v);
    __half h1 = __float2half_rn(v - __half2float(h0));
    g_B0[(size_t)n * H_DIM + k] = h0;
    g_B1[(size_t)n * H_DIM + k] = h1;
}

// ---------------------------------------------------------------------------
// GEMM (1 term, 4-deep pipeline): logits16 = fp16(A0*B0 + b).
// BM=128, BN=128, BK=32; 256 threads; 8 warps (2x4), warp tile 64x32.
// 4 smem buffers, cp.async.wait_group 2 steady state.
// ---------------------------------------------------------------------------
#define STG_BYTES   20480          // A(10240) + B(10240)
#define NBUF        4
#define SMEM_BYTES  (NBUF * STG_BYTES)

__global__ __launch_bounds__(256, 2) void gemm_kernel(const float* __restrict__ bias) {
    extern __shared__ char smem[];
    const uint32_t sb = smem_u32(smem);
    const int tid  = threadIdx.x;
    const int wid  = tid >> 5;
    const int lane = tid & 31;
    const int wm = wid >> 2;
    const int wn = wid & 3;
    const int m0 = blockIdx.y * 128;
    const int n0 = blockIdx.x * 128;

    float acc[4][4][4];
#pragma unroll
    for (int mf = 0; mf < 4; mf++)
#pragma unroll
        for (int nf = 0; nf < 4; nf++)
#pragma unroll
            for (int c = 0; c < 4; c++) acc[mf][nf][c] = 0.0f;

    const int r0 = tid >> 2;
    const int kc = tid & 3;
    const __half* pA0 = g_A0 + (size_t)(m0 + r0) * H_DIM + kc * 8;
    const __half* pB0 = g_B0 + (size_t)(n0 + r0) * H_DIM + kc * 8;
    const uint32_t sA = sb + r0 * 80 + kc * 16;
    const size_t ROW64 = (size_t)64 * H_DIM;

    // issue stage s into buffer s&3 (empty commit past the end keeps the
    // group count uniform so wait_group 2 always certifies stage s)
    auto issue_stage = [&](int s) {
        if (s < 16) {
            const int off = s * 32;
            const uint32_t buf = (uint32_t)(s & (NBUF - 1)) * STG_BYTES;
            cp_async16(sA + buf,                 pA0 + off);
            cp_async16(sA + buf + 5120,          pA0 + off + ROW64);
            cp_async16(sA + buf + 10240,         pB0 + off);
            cp_async16(sA + buf + 10240 + 5120,  pB0 + off + ROW64);
        }
        asm volatile("cp.async.commit_group;" ::: "memory");
    };

    issue_stage(0);
    issue_stage(1);
    issue_stage(2);

    const int a_row = wm * 64 + (lane & 15);
    const int a_kc  = (lane >> 4) * 16;
    const int b_row = wn * 32 + ((lane >> 4) & 1) * 8 + (lane & 7);
    const int b_kc  = ((lane >> 3) & 1) * 16;

    for (int s = 0; s < 16; s++) {
        asm volatile("cp.async.wait_group 2;" ::: "memory");  // stage s done
        __syncthreads();                   // visible to all; MMA(s-1) done by all
        issue_stage(s + 3);                // buffer (s+3)&3 == (s-1)&3 — safe

        const uint32_t abase = sb + (uint32_t)(s & (NBUF - 1)) * STG_BYTES;
        const uint32_t bbase = abase + 10240;

#pragma unroll
        for (int ks = 0; ks < 2; ks++) {
            uint32_t Bf[8];
#pragma unroll
            for (int p = 0; p < 2; p++)
                ldsm4(&Bf[p * 4], bbase + (b_row + p * 16) * 80 + ks * 32 + b_kc);

            uint32_t Af[4][4];
#pragma unroll
            for (int mf = 0; mf < 4; mf++)
                ldsm4(Af[mf], abase + (a_row + mf * 16) * 80 + ks * 32 + a_kc);
#pragma unroll
            for (int mf = 0; mf < 4; mf++)
#pragma unroll
                for (int nf = 0; nf < 4; nf++)
                    mma16816(acc[mf][nf], Af[mf], &Bf[nf * 2]);
        }
    }

    const int gID = lane >> 2;
    const int tig = lane & 3;
    float2 bv[4];
#pragma unroll
    for (int nf = 0; nf < 4; nf++)
        bv[nf] = *reinterpret_cast<const float2*>(bias + n0 + wn * 32 + nf * 8 + tig * 2);

#pragma unroll
    for (int mf = 0; mf < 4; mf++) {
        const int m = m0 + wm * 64 + mf * 16 + gID;
#pragma unroll
        for (int nf = 0; nf < 4; nf++) {
            const int n = n0 + wn * 32 + nf * 8 + tig * 2;
            __half2 h0 = __floats2half2_rn(acc[mf][nf][0] + bv[nf].x,
                                           acc[mf][nf][1] + bv[nf].y);
            __half2 h1 = __floats2half2_rn(acc[mf][nf][2] + bv[nf].x,
                                           acc[mf][nf][3] + bv[nf].y);
            *reinterpret_cast<__half2*>(g_logits + (size_t)m * GVDIM + n)       = h0;
            *reinterpret_cast<__half2*>(g_logits + (size_t)(m + 8) * GVDIM + n) = h1;
        }
    }
}

// ---------------------------------------------------------------------------
// Exact logit: fp32 A row . (B0+B1) column, warp-collective.
// ---------------------------------------------------------------------------
__device__ float warp_dot(const float* __restrict__ arow,
                          const __half* __restrict__ b0row,
                          const __half* __restrict__ b1row, int lane) {
    const unsigned FULL = 0xffffffffu;
    float s = 0.0f;
    const float4*   a4  = reinterpret_cast<const float4*>(arow) + lane * 4;
    const __half2*  b02 = reinterpret_cast<const __half2*>(b0row) + lane * 8;
    const __half2*  b12 = reinterpret_cast<const __half2*>(b1row) + lane * 8;
#pragma unroll
    for (int i = 0; i < 4; i++) {
        float4 a  = a4[i];
        float2 p0 = __half22float2(b02[2 * i]);
        float2 q0 = __half22float2(b12[2 * i]);
        float2 p1 = __half22float2(b02[2 * i + 1]);
        float2 q1 = __half22float2(b12[2 * i + 1]);
        s = fmaf(a.x, p0.x + q0.x, s);
        s = fmaf(a.y, p0.y + q0.y, s);
        s = fmaf(a.z, p1.x + q1.x, s);
        s = fmaf(a.w, p1.y + q1.y, s);
    }
#pragma unroll
    for (int off = 16; off; off >>= 1)
        s += __shfl_xor_sync(FULL, s, off);
    return s;
}

// ---------------------------------------------------------------------------
// Epilogue: one warp per (n,g) pair; 8 pairs/warp; 2048 blocks x 256 thr.
// Approx z from fp16 1-term logits; margin 1e-2 covers quantization+log err.
// Single candidate (~99% of rows) -> done. Else exact fp32 dots (rare).
// ---------------------------------------------------------------------------
__global__ __launch_bounds__(256) void epilogue_kernel(
    const float* __restrict__ A,
    const float* __restrict__ bias,
    const float* __restrict__ gumbel_u,
    const float* __restrict__ codevectors,
    float* __restrict__ out)
{
    const unsigned FULL = 0xffffffffu;
    __shared__ float smar[GVDIM];
    const int tid  = threadIdx.x;
    const int warp = blockIdx.x * 8 + (tid >> 5);
    const int lane = tid & 31;

    for (int i = tid; i < GVDIM; i += 256) smar[i] = 0.0f;
    __syncthreads();

    float macc[2][10];
#pragma unroll
    for (int g = 0; g < 2; g++)
#pragma unroll
        for (int j = 0; j < 10; j++) macc[g][j] = 0.0f;

    const int p0 = warp * 8;
    for (int i = 0; i < 8; i++) {
        const int p = p0 + i;
        const int n = p >> 1;
        const int g = p & 1;
        const __half* lrow = g_logits + (size_t)n * GVDIM + g * VNUM;
        const float*  urow = gumbel_u + (size_t)p * VNUM;

        float l[10], u[10], za[10];
#pragma unroll
        for (int jj = 0; jj < 5; jj++) {
            const __half2 lh = *reinterpret_cast<const __half2*>(lrow + 2 * (lane + 32 * jj));
            float2 lf = __half22float2(lh);
            float2 uf = *reinterpret_cast<const float2*>(urow + 2 * (lane + 32 * jj));
            l[2 * jj] = lf.x; l[2 * jj + 1] = lf.y;
            u[2 * jj] = uf.x; u[2 * jj + 1] = uf.y;
        }

        // ---- approx pass, reliable for all u ----
        float lmax = -3.4e38f, zax = -3.4e38f;
#pragma unroll
        for (int s = 0; s < 10; s++) {
            lmax = fmaxf(lmax, l[s]);
            const float t1 = 1.0f - u[s];
            const float ws = t1 * fmaf(t1, fmaf(t1, 0.33333334f, 0.5f), 1.0f);
            const float wm = -__logf(u[s]);
            const float w  = (u[s] > 0.99f) ? ws : wm;
            za[s] = l[s] - __logf(w);
            zax = fmaxf(zax, za[s]);
        }
#pragma unroll
        for (int off = 16; off; off >>= 1) {
            lmax = fmaxf(lmax, __shfl_xor_sync(FULL, lmax, off));
            zax  = fmaxf(zax,  __shfl_xor_sync(FULL, zax,  off));
        }
        const float thresh = zax - 1e-2f;

        // ---- candidate ballots ----
        unsigned bal[10];
        int total = 0;
#pragma unroll
        for (int s = 0; s < 10; s++) {
            bal[s] = __ballot_sync(FULL, za[s] >= thresh);
            total += __popc(bal[s]);
        }

        int ibest;
        if (total == 1) {
            ibest = 0;
#pragma unroll
            for (int s = 0; s < 10; s++)
                if (bal[s]) {
                    const int ln = __ffs(bal[s]) - 1;
                    ibest = 64 * (s >> 1) + 2 * ln + (s & 1);
                }
        } else {
            // rare: exact fp32 recompute of all candidates
            float zb = -3.4e38f;
            int   ib = 0x7fffffff;
            const float*  arow = A + (size_t)n * H_DIM;
            const __half* b0b  = g_B0 + (size_t)(g * VNUM) * H_DIM;
            const __half* b1b  = g_B1 + (size_t)(g * VNUM) * H_DIM;
#pragma unroll
            for (int s = 0; s < 10; s++) {
                unsigned m = bal[s];
                while (m) {
                    const int ln = __ffs(m) - 1; m &= m - 1;
                    const int v  = 64 * (s >> 1) + 2 * ln + (s & 1);
                    const float uc = __shfl_sync(FULL, u[s], ln);
                    const float dot = warp_dot(arow, b0b + (size_t)v * H_DIM,
                                               b1b + (size_t)v * H_DIM, lane);
                    const float w = neg_log_acc(uc);
                    const float z = dot + bias[g * VNUM + v] - acc_logf(w);
                    if (z > zb || (z == zb && v < ib)) { zb = z; ib = v; }
                }
            }
            ibest = ib;
        }

        // ---- noise-free softmax -> marginal partials (fp16 logits) ----
        float e[10];
        float ssum = 0.0f;
#pragma unroll
        for (int s = 0; s < 10; s++) { e[s] = __expf(l[s] - lmax); ssum += e[s]; }
#pragma unroll
        for (int off = 16; off; off >>= 1)
            ssum += __shfl_xor_sync(FULL, ssum, off);
        const float rs = 1.0f / ssum;
#pragma unroll
        for (int s = 0; s < 10; s++) macc[g][s] = fmaf(e[s], rs, macc[g][s]);

        // ---- codes gather ----
        const float4* cvp = reinterpret_cast<const float4*>(
            codevectors + ((size_t)(g * VNUM + ibest)) * DDIM);
        float4* op = reinterpret_cast<float4*>(out + (size_t)n * 256 + g * DDIM);
        op[lane] = cvp[lane];
    }

#pragma unroll
    for (int g = 0; g < 2; g++)
#pragma unroll
        for (int jj = 0; jj < 5; jj++)
#pragma unroll
            for (int q = 0; q < 2; q++)
                atomicAdd(&smar[g * VNUM + 64 * jj + 2 * lane + q], macc[g][2 * jj + q]);
    __syncthreads();
    for (int i = tid; i < GVDIM; i += 256)
        atomicAdd(&g_marginal[i], smar[i]);
}

// ---------------------------------------------------------------------------
__global__ void perp_kernel(float* __restrict__ out, int out_size) {
    __shared__ float red[2];
    const int i    = threadIdx.x;          // 0..639
    const int lane = i & 31;
    if (i < 2) red[i] = 0.0f;
    __syncthreads();
    const float m = g_marginal[i] * (1.0f / (float)N_FRAMES);
    float part = m * acc_logf(m + 1e-7f);
#pragma unroll
    for (int off = 16; off; off >>= 1)
        part += __shfl_xor_sync(0xffffffffu, part, off);
    if (lane == 0) atomicAdd(&red[i >= VNUM ? 1 : 0], part);
    __syncthreads();
    if (i == 0) {
        const float perp = __expf(-red[0]) + __expf(-red[1]);
        if (out_size > N_FRAMES * 256) out[(size_t)N_FRAMES * 256] = perp;
    }
}

// ---------------------------------------------------------------------------
extern "C" void kernel_launch(void* const* d_in, const int* in_sizes, int n_in,
                              void* d_out, int out_size) {
    const float* hs = (const float*)d_in[0];   // [16,4096,512]
    const float* W  = (const float*)d_in[1];   // [512,640]
    const float* b  = (const float*)d_in[2];   // [640]
    const float* cv = (const float*)d_in[3];   // [640,128]
    const float* gu = (const float*)d_in[4];   // [131072,320]
    float* out = (float*)d_out;

    split_b_kernel<<<GVDIM, 512>>>(W);
    split_a_kernel<<<8192, 1024>>>(hs);

    cudaFuncSetAttribute(gemm_kernel,
                         cudaFuncAttributeMaxDynamicSharedMemorySize, SMEM_BYTES);
    gemm_kernel<<<dim3(5, 512), 256, SMEM_BYTES>>>(b);

    epilogue_kernel<<<2048, 256>>>(hs, b, gu, cv, out);
    perp_kernel<<<1, GVDIM>>>(out, out_size);
}